// round 10
// baseline (speedup 1.0000x reference)
#include <cuda_runtime.h>
#include <cstdint>
#include <cstddef>

// ---------------- problem geometry ----------------
#define IN_W   512
#define IN_H   512
#define OUT_W  1024
#define OUT_H  1024
#define NB     32
#define NC     3

#define TX     128
#define TY     32
#define ITR    24          // input tile rows  (TY/2 + 8)
#define ITC    72          // input tile cols  (TX/2 + 8)
#define NTILES (8 * 32 * NB * NC)   // 24576 CTAs in resize grid
#define TILES_PER_IMG (8 * 32 * NC) // 768

// ---------------- compile-time Lanczos4 weights (2 phases) ----------------
struct W16 { float w0[8]; float w1[8]; };

constexpr W16 make_weights() {
    const double sq  = 0.70710678118654752440;
    const double s1  = 0.19509032201612826785;
    const double s3  = 0.55557023301960222474;
    const double s5  = 0.83146961230254523708;
    const double s7  = 0.98078528040323044913;
    const double pi  = 3.14159265358979323846;
    const double d[8]    = { 3.75,  2.75,  1.75,  0.75, -0.25, -1.25, -2.25, -3.25 };
    const double spd[8]  = { -sq ,  sq  , -sq  ,  sq  , -sq  ,  sq  , -sq  ,  sq   };
    const double spd4[8] = {  s1 ,  s5  ,  s7  ,  s3  , -s1  , -s5  , -s7  , -s3   };
    double raw[8] = {};
    double s = 0.0;
    for (int t = 0; t < 8; ++t) {
        raw[t] = spd[t] * spd4[t] * 4.0 / (pi * pi * d[t] * d[t]);
        s += raw[t];
    }
    W16 r{};
    for (int t = 0; t < 8; ++t) {
        r.w0[t]     = (float)(raw[t] / s);  // phase 0.75 (even outputs)
        r.w1[7 - t] = (float)(raw[t] / s);  // phase 0.25 (odd) = mirror
    }
    return r;
}
constexpr W16 KW = make_weights();

// ---------------- min/max scratch (fully rewritten every call) ----------
__device__ float g_pmin[NTILES];
__device__ float g_pmax[NTILES];
__device__ float g_min[NB];
__device__ float g_max[NB];

// ---------------- reduce kernel: per-image min/max from tile partials ----
__global__ void __launch_bounds__(256) k_reduce() {
    const int img  = blockIdx.x;
    const int base = img * TILES_PER_IMG;
    const int tid  = threadIdx.x;
    float mn = 3.0e38f, mx = -3.0e38f;
    for (int i = tid; i < TILES_PER_IMG; i += 256) {
        mn = fminf(mn, g_pmin[base + i]);
        mx = fmaxf(mx, g_pmax[base + i]);
    }
#pragma unroll
    for (int o = 16; o; o >>= 1) {
        mn = fminf(mn, __shfl_xor_sync(0xFFFFFFFFu, mn, o));
        mx = fmaxf(mx, __shfl_xor_sync(0xFFFFFFFFu, mx, o));
    }
    __shared__ float red[16];
    const int wid = tid >> 5;
    if ((tid & 31) == 0) { red[wid] = mn; red[8 + wid] = mx; }
    __syncthreads();
    if (tid == 0) {
        float m0 = red[0], m1 = red[8];
#pragma unroll
        for (int i = 1; i < 8; ++i) {
            m0 = fminf(m0, red[i]);
            m1 = fmaxf(m1, red[8 + i]);
        }
        g_min[img] = m0;
        g_max[img] = m1;
    }
}

// ---------------- main resize kernel ----------------
// PASS 0: resize tile -> per-tile min/max into scratch.
// PASS 1: resize tile -> renormalize -> store float32 (uint8-valued).
template <int PASS>
__global__ void __launch_bounds__(256, 4)
k_resize(const float* __restrict__ x, float* __restrict__ out)
{
    __shared__ __align__(16) float s_in[ITR * ITC];   // input tile
    __shared__ __align__(16) float s_it[TY * ITC];    // H-resampled intermediate

    const int tid = threadIdx.x;
    const int bc  = blockIdx.z;
    const int img = bc / 3;
    const int ox0 = blockIdx.x * TX;
    const int oy0 = blockIdx.y * TY;
    const int ix0 = (ox0 >> 1) - 4;
    const int iy0 = (oy0 >> 1) - 4;
    const float* __restrict__ src = x + (size_t)bc * (IN_W * IN_H);

    const float w0[8] = { KW.w0[0], KW.w0[1], KW.w0[2], KW.w0[3],
                          KW.w0[4], KW.w0[5], KW.w0[6], KW.w0[7] };
    const float w1[8] = { KW.w1[0], KW.w1[1], KW.w1[2], KW.w1[3],
                          KW.w1[4], KW.w1[5], KW.w1[6], KW.w1[7] };

    // ---- load input tile ----
    const bool interior = (ix0 >= 0) & (ix0 + ITC <= IN_W) &
                          (iy0 >= 0) & (iy0 + ITR <= IN_H);
    if (interior) {
        // 24 rows x 18 float4 = 432 vector loads, 16B-aligned (ix0 = 64bx-4)
        const float4* s4 = reinterpret_cast<const float4*>(src + (size_t)iy0 * IN_W + ix0);
        float4* d4 = reinterpret_cast<float4*>(s_in);
#pragma unroll
        for (int it = 0; it < 2; ++it) {
            int e = tid + it * 256;
            if (e < 432) {
                int r = e / 18;
                int c = e - r * 18;
                d4[e] = __ldg(s4 + (size_t)r * (IN_W / 4) + c);
            }
        }
    } else {
        for (int e = tid; e < ITR * ITC; e += 256) {
            int r = e / ITC;
            int c = e - r * ITC;
            int gy = min(max(iy0 + r, 0), IN_H - 1);
            int gx = min(max(ix0 + c, 0), IN_W - 1);
            s_in[e] = __ldg(src + gy * IN_W + gx);
        }
    }
    __syncthreads();

    // ---- H (vertical) resample: unit = (col-pair, 4 out rows); 36*8 = 288 units
    // LDS.64 column pairs; .x/.y feed scalar FFMA directly (no repacking).
    {
        const float2* sin2 = reinterpret_cast<const float2*>(s_in);
        float2*       sit2 = reinterpret_cast<float2*>(s_it);
#pragma unroll
        for (int it = 0; it < 2; ++it) {
            const int u = tid + it * 256;
            if (it == 0 || u < 288) {
                const int rg = u / 36;          // output rows 4rg..4rg+3
                const int cp = u - rg * 36;     // columns 2cp, 2cp+1
                float2 v[10];
#pragma unroll
                for (int k = 0; k < 10; ++k)
                    v[k] = sin2[(2 * rg + k) * (ITC / 2) + cp];

                float a0 = 0.f, a1 = 0.f, a2 = 0.f, a3 = 0.f;   // col .x, rows 0..3
                float b0 = 0.f, b1 = 0.f, b2 = 0.f, b3 = 0.f;   // col .y
#pragma unroll
                for (int t = 0; t < 8; ++t) {
                    a0 = fmaf(w0[t], v[t].x,     a0);
                    a1 = fmaf(w1[t], v[t + 1].x, a1);
                    a2 = fmaf(w0[t], v[t + 1].x, a2);
                    a3 = fmaf(w1[t], v[t + 2].x, a3);
                    b0 = fmaf(w0[t], v[t].y,     b0);
                    b1 = fmaf(w1[t], v[t + 1].y, b1);
                    b2 = fmaf(w0[t], v[t + 1].y, b2);
                    b3 = fmaf(w1[t], v[t + 2].y, b3);
                }
                float2* o = sit2 + (4 * rg) * (ITC / 2) + cp;
                o[0 * (ITC / 2)] = make_float2(a0, b0);
                o[1 * (ITC / 2)] = make_float2(a1, b1);
                o[2 * (ITC / 2)] = make_float2(a2, b2);
                o[3 * (ITC / 2)] = make_float2(a3, b3);
            }
        }
    }
    __syncthreads();

    // ---- pass-1 renorm constants: y = min_or_max(C*im, D*im + E) ----
    float Cc = 255.0f, D1 = 255.0f, E1 = 0.0f;
    bool fast = true;
    if (PASS == 1) {
        float mn = g_min[img];
        float mx = g_max[img];
        if ((mx - mn) > 1.0f) {
            const float ott = 1.0f / 255.0f, ubt = -10.0f / 255.0f;
            const float c = 1.0f - ott, d = 1.0f - ubt;
            float otr = mx - 1.0f;
            float a1  = ott / (otr != 0.0f ? otr : 1.0f);
            Cc = 255.0f * c * d;            // segment for im < 1
            D1 = 255.0f * d * a1;           // segment for im > 1
            E1 = Cc - D1;                   // continuity at im = 1
            fast = (D1 <= Cc);              // min-composition valid
        }
    }

    // ---- W (horizontal) resample: unit = (row, 16 out cols); 32*8 = 256 units
    // window = v[0..15]: even col 2m <- w0 . v[m..m+7], odd <- w1 . v[m+1..m+8]
    float lmin = 3.0e38f, lmax = -3.0e38f;
    {
        const int h = tid & 7;              // output cols 16h..16h+15
        const int r = tid >> 3;             // output row (tile-local)

        const float4* p = reinterpret_cast<const float4*>(s_it + r * ITC + 8 * h);
        const float4 qa = p[0], qb = p[1], qc = p[2], qd = p[3];
        const float v[16] = { qa.x, qa.y, qa.z, qa.w,
                              qb.x, qb.y, qb.z, qb.w,
                              qc.x, qc.y, qc.z, qc.w,
                              qd.x, qd.y, qd.z, qd.w };

        size_t obase = 0;
        if (PASS == 1)
            obase = (size_t)bc * (OUT_H * OUT_W)
                  + (size_t)(oy0 + r) * OUT_W + ox0 + 16 * h;

#pragma unroll
        for (int half = 0; half < 2; ++half) {
            const int m0 = half * 4;        // m = m0..m0+3 -> output cols 2m..
            float o0 = 0.f, o1 = 0.f, o2 = 0.f, o3 = 0.f;
            float o4 = 0.f, o5 = 0.f, o6 = 0.f, o7 = 0.f;
#pragma unroll
            for (int t = 0; t < 8; ++t) {
                o0 = fmaf(w0[t], v[m0 + t],     o0);
                o1 = fmaf(w1[t], v[m0 + t + 1], o1);
                o2 = fmaf(w0[t], v[m0 + t + 1], o2);
                o3 = fmaf(w1[t], v[m0 + t + 2], o3);
                o4 = fmaf(w0[t], v[m0 + t + 2], o4);
                o5 = fmaf(w1[t], v[m0 + t + 3], o5);
                o6 = fmaf(w0[t], v[m0 + t + 3], o6);
                o7 = fmaf(w1[t], v[m0 + t + 4], o7);
            }

            if (PASS == 0) {
                float mn0 = fminf(fminf(o0, o1), fminf(o2, o3));
                float mn1 = fminf(fminf(o4, o5), fminf(o6, o7));
                float mx0 = fmaxf(fmaxf(o0, o1), fmaxf(o2, o3));
                float mx1 = fmaxf(fmaxf(o4, o5), fmaxf(o6, o7));
                lmin = fminf(lmin, fminf(mn0, mn1));
                lmax = fmaxf(lmax, fmaxf(mx0, mx1));
            } else {
                const float oo[8] = { o0, o1, o2, o3, o4, o5, o6, o7 };
                float res[8];
#pragma unroll
                for (int q = 0; q < 8; ++q) {
                    float y1 = oo[q] * Cc;
                    float y2 = fmaf(oo[q], D1, E1);
                    float y  = fast ? fminf(y1, y2) : fmaxf(y1, y2);
                    res[q] = (float)min(__float2uint_rz(y), 255u);
                }
                float4 q1 = { res[0], res[1], res[2], res[3] };
                float4 q2 = { res[4], res[5], res[6], res[7] };
                *reinterpret_cast<float4*>(out + obase + 8 * half)     = q1;
                *reinterpret_cast<float4*>(out + obase + 8 * half + 4) = q2;
            }
        }
    }

    if (PASS == 0) {
#pragma unroll
        for (int o = 16; o; o >>= 1) {
            lmin = fminf(lmin, __shfl_xor_sync(0xFFFFFFFFu, lmin, o));
            lmax = fmaxf(lmax, __shfl_xor_sync(0xFFFFFFFFu, lmax, o));
        }
        __shared__ float red[16];
        const int wid = tid >> 5;
        if ((tid & 31) == 0) { red[wid] = lmin; red[8 + wid] = lmax; }
        __syncthreads();
        if (tid == 0) {
            float m0 = red[0], m1 = red[8];
#pragma unroll
            for (int i = 1; i < 8; ++i) {
                m0 = fminf(m0, red[i]);
                m1 = fmaxf(m1, red[8 + i]);
            }
            int lid = blockIdx.x + 8 * (blockIdx.y + 32 * blockIdx.z);
            g_pmin[lid] = m0;
            g_pmax[lid] = m1;
        }
    }
}

extern "C" void kernel_launch(void* const* d_in, const int* in_sizes, int n_in,
                              void* d_out, int out_size) {
    const float* x = (const float*)d_in[0];
    float* out = (float*)d_out;

    dim3 grid(OUT_W / TX, OUT_H / TY, NB * NC);   // 8 x 32 x 96
    k_resize<0><<<grid, 256>>>(x, nullptr);       // resize + per-tile min/max
    k_reduce<<<NB, 256>>>();                      // per-image min/max
    k_resize<1><<<grid, 256>>>(x, out);           // resize + renorm + f32(u8) store
}

// round 13
// speedup vs baseline: 1.1416x; 1.1416x over previous
#include <cuda_runtime.h>
#include <cstdint>
#include <cstddef>

// ---------------- problem geometry ----------------
#define IN_W   512
#define IN_H   512
#define OUT_W  1024
#define OUT_H  1024
#define NB     32
#define NC     3

#define TX     128
#define TY     32
#define ITR    24          // input tile rows  (TY/2 + 8)
#define ITC    72          // input tile cols  (TX/2 + 8)
#define NTILES (8 * 32 * NB * NC)   // 24576 CTAs in resize grid
#define TILES_PER_IMG (8 * 32 * NC) // 768

// ---------------- compile-time Lanczos4 weights (2 phases) ----------------
struct W16 { float w0[8]; float w1[8]; };

constexpr W16 make_weights() {
    const double sq  = 0.70710678118654752440;
    const double s1  = 0.19509032201612826785;
    const double s3  = 0.55557023301960222474;
    const double s5  = 0.83146961230254523708;
    const double s7  = 0.98078528040323044913;
    const double pi  = 3.14159265358979323846;
    const double d[8]    = { 3.75,  2.75,  1.75,  0.75, -0.25, -1.25, -2.25, -3.25 };
    const double spd[8]  = { -sq ,  sq  , -sq  ,  sq  , -sq  ,  sq  , -sq  ,  sq   };
    const double spd4[8] = {  s1 ,  s5  ,  s7  ,  s3  , -s1  , -s5  , -s7  , -s3   };
    double raw[8] = {};
    double s = 0.0;
    for (int t = 0; t < 8; ++t) {
        raw[t] = spd[t] * spd4[t] * 4.0 / (pi * pi * d[t] * d[t]);
        s += raw[t];
    }
    W16 r{};
    for (int t = 0; t < 8; ++t) {
        r.w0[t]     = (float)(raw[t] / s);  // phase 0.75 (even outputs)
        r.w1[7 - t] = (float)(raw[t] / s);  // phase 0.25 (odd) = mirror
    }
    return r;
}
constexpr W16 KW = make_weights();

// ---------------- min/max scratch (fully rewritten every call) ----------
__device__ float g_pmin[NTILES];
__device__ float g_pmax[NTILES];
__device__ float g_min[NB];
__device__ float g_max[NB];

// ---------------- reduce kernel: per-image min/max from tile partials ----
__global__ void __launch_bounds__(256) k_reduce() {
    const int img  = blockIdx.x;
    const int base = img * TILES_PER_IMG;
    const int tid  = threadIdx.x;
    float mn = 3.0e38f, mx = -3.0e38f;
    for (int i = tid; i < TILES_PER_IMG; i += 256) {
        mn = fminf(mn, g_pmin[base + i]);
        mx = fmaxf(mx, g_pmax[base + i]);
    }
#pragma unroll
    for (int o = 16; o; o >>= 1) {
        mn = fminf(mn, __shfl_xor_sync(0xFFFFFFFFu, mn, o));
        mx = fmaxf(mx, __shfl_xor_sync(0xFFFFFFFFu, mx, o));
    }
    __shared__ float red[16];
    const int wid = tid >> 5;
    if ((tid & 31) == 0) { red[wid] = mn; red[8 + wid] = mx; }
    __syncthreads();
    if (tid == 0) {
        float m0 = red[0], m1 = red[8];
#pragma unroll
        for (int i = 1; i < 8; ++i) {
            m0 = fminf(m0, red[i]);
            m1 = fmaxf(m1, red[8 + i]);
        }
        g_min[img] = m0;
        g_max[img] = m1;
    }
}

// ---------------- H-stage unit: 8 output rows for one column ----------
// Output rows 8rg..8rg+7 need input rows 4rg..4rg+11 (12-row window).
__device__ __forceinline__ void h_unit(const float* __restrict__ s_in,
                                       float* __restrict__ s_it,
                                       const float* w0, const float* w1,
                                       int rg, int c)
{
    float v[12];
#pragma unroll
    for (int k = 0; k < 12; ++k)
        v[k] = s_in[(4 * rg + k) * ITC + c];

    float o0 = 0.f, o1 = 0.f, o2 = 0.f, o3 = 0.f;
    float o4 = 0.f, o5 = 0.f, o6 = 0.f, o7 = 0.f;
#pragma unroll
    for (int t = 0; t < 8; ++t) {
        o0 = fmaf(w0[t], v[t],     o0);   // row 8rg   (even)
        o1 = fmaf(w1[t], v[t + 1], o1);   // row 8rg+1 (odd)
        o2 = fmaf(w0[t], v[t + 1], o2);   // row 8rg+2 (even)
        o3 = fmaf(w1[t], v[t + 2], o3);   // row 8rg+3 (odd)
        o4 = fmaf(w0[t], v[t + 2], o4);   // row 8rg+4 (even)
        o5 = fmaf(w1[t], v[t + 3], o5);   // row 8rg+5 (odd)
        o6 = fmaf(w0[t], v[t + 3], o6);   // row 8rg+6 (even)
        o7 = fmaf(w1[t], v[t + 4], o7);   // row 8rg+7 (odd)
    }
    float* o = s_it + (8 * rg) * ITC + c;
    o[0 * ITC] = o0;  o[1 * ITC] = o1;
    o[2 * ITC] = o2;  o[3 * ITC] = o3;
    o[4 * ITC] = o4;  o[5 * ITC] = o5;
    o[6 * ITC] = o6;  o[7 * ITC] = o7;
}

// ---------------- main resize kernel ----------------
// PASS 0: resize tile -> per-tile min/max into scratch.
// PASS 1: resize tile -> renormalize -> store float32 (uint8-valued).
template <int PASS>
__global__ void __launch_bounds__(256, 4)
k_resize(const float* __restrict__ x, float* __restrict__ out)
{
    __shared__ __align__(16) float s_in[ITR * ITC];   // input tile
    __shared__ __align__(16) float s_it[TY * ITC];    // H-resampled intermediate

    const int tid = threadIdx.x;
    const int bc  = blockIdx.z;
    const int img = bc / 3;
    const int ox0 = blockIdx.x * TX;
    const int oy0 = blockIdx.y * TY;
    const int ix0 = (ox0 >> 1) - 4;
    const int iy0 = (oy0 >> 1) - 4;
    const float* __restrict__ src = x + (size_t)bc * (IN_W * IN_H);

    const float w0[8] = { KW.w0[0], KW.w0[1], KW.w0[2], KW.w0[3],
                          KW.w0[4], KW.w0[5], KW.w0[6], KW.w0[7] };
    const float w1[8] = { KW.w1[0], KW.w1[1], KW.w1[2], KW.w1[3],
                          KW.w1[4], KW.w1[5], KW.w1[6], KW.w1[7] };

    // ---- load input tile ----
    const bool interior = (ix0 >= 0) & (ix0 + ITC <= IN_W) &
                          (iy0 >= 0) & (iy0 + ITR <= IN_H);
    if (interior) {
        // 24 rows x 18 float4 = 432 vector loads, 16B-aligned (ix0 = 64bx-4)
        const float4* s4 = reinterpret_cast<const float4*>(src + (size_t)iy0 * IN_W + ix0);
        float4* d4 = reinterpret_cast<float4*>(s_in);
#pragma unroll
        for (int it = 0; it < 2; ++it) {
            int e = tid + it * 256;
            if (e < 432) {
                int r = e / 18;
                int c = e - r * 18;
                d4[e] = __ldg(s4 + (size_t)r * (IN_W / 4) + c);
            }
        }
    } else {
        for (int e = tid; e < ITR * ITC; e += 256) {
            int r = e / ITC;
            int c = e - r * ITC;
            int gy = min(max(iy0 + r, 0), IN_H - 1);
            int gx = min(max(ix0 + c, 0), IN_W - 1);
            s_in[e] = __ldg(src + gy * IN_W + gx);
        }
    }
    __syncthreads();

    // ---- H (vertical) resample: 288 units of (col, 8 out rows) ----
    // round 1: cols 0..63 x rowgroups 0..3 (256 units, shift/mask mapping)
    // round 2: cols 64..71 x rowgroups 0..3 (32 units = warp 0 only)
    h_unit(s_in, s_it, w0, w1, tid >> 6, tid & 63);
    if (tid < 32)
        h_unit(s_in, s_it, w0, w1, tid >> 3, 64 + (tid & 7));
    __syncthreads();

    // ---- pass-1 renorm constants: y = min_or_max(C*im, D*im + E) ----
    float Cc = 255.0f, D1 = 255.0f, E1 = 0.0f;
    bool fast = true;
    if (PASS == 1) {
        float mn = g_min[img];
        float mx = g_max[img];
        if ((mx - mn) > 1.0f) {
            const float ott = 1.0f / 255.0f, ubt = -10.0f / 255.0f;
            const float c = 1.0f - ott, d = 1.0f - ubt;
            float otr = mx - 1.0f;
            float a1  = ott / (otr != 0.0f ? otr : 1.0f);
            Cc = 255.0f * c * d;            // segment for im < 1
            D1 = 255.0f * d * a1;           // segment for im > 1
            E1 = Cc - D1;                   // continuity at im = 1
            fast = (D1 <= Cc);              // min-composition valid
        }
    }

    // ---- W (horizontal) resample: unit = (row, 8 out cols); 32*16 = 512 units
    float lmin = 3.0e38f, lmax = -3.0e38f;

#pragma unroll
    for (int it = 0; it < 2; ++it) {
        const int u = tid + it * 256;
        const int h = u & 15;               // output cols 8h..8h+7
        const int r = u >> 4;               // output row (tile-local)

        const float4* p = reinterpret_cast<const float4*>(s_it + r * ITC + 4 * h);
        const float4 qa = p[0], qb = p[1], qc = p[2];
        const float v[12] = { qa.x, qa.y, qa.z, qa.w,
                              qb.x, qb.y, qb.z, qb.w,
                              qc.x, qc.y, qc.z, qc.w };

        float o0 = 0.f, o1 = 0.f, o2 = 0.f, o3 = 0.f;
        float o4 = 0.f, o5 = 0.f, o6 = 0.f, o7 = 0.f;
#pragma unroll
        for (int t = 0; t < 8; ++t) {
            o0 = fmaf(w0[t], v[t],     o0);
            o1 = fmaf(w1[t], v[t + 1], o1);
            o2 = fmaf(w0[t], v[t + 1], o2);
            o3 = fmaf(w1[t], v[t + 2], o3);
            o4 = fmaf(w0[t], v[t + 2], o4);
            o5 = fmaf(w1[t], v[t + 3], o5);
            o6 = fmaf(w0[t], v[t + 3], o6);
            o7 = fmaf(w1[t], v[t + 4], o7);
        }

        if (PASS == 0) {
            float mn0 = fminf(fminf(o0, o1), fminf(o2, o3));
            float mn1 = fminf(fminf(o4, o5), fminf(o6, o7));
            float mx0 = fmaxf(fmaxf(o0, o1), fmaxf(o2, o3));
            float mx1 = fmaxf(fmaxf(o4, o5), fmaxf(o6, o7));
            lmin = fminf(lmin, fminf(mn0, mn1));
            lmax = fmaxf(lmax, fmaxf(mx0, mx1));
        } else {
            const float oo[8] = { o0, o1, o2, o3, o4, o5, o6, o7 };
            float res[8];
#pragma unroll
            for (int q = 0; q < 8; ++q) {
                float y1 = oo[q] * Cc;
                float y2 = fmaf(oo[q], D1, E1);
                float y  = fast ? fminf(y1, y2) : fmaxf(y1, y2);
                res[q] = (float)min(__float2uint_rz(y), 255u);
            }
            float4 q1 = { res[0], res[1], res[2], res[3] };
            float4 q2 = { res[4], res[5], res[6], res[7] };
            size_t o = (size_t)bc * (OUT_H * OUT_W)
                     + (size_t)(oy0 + r) * OUT_W + ox0 + 8 * h;
            *reinterpret_cast<float4*>(out + o)     = q1;
            *reinterpret_cast<float4*>(out + o + 4) = q2;
        }
    }

    if (PASS == 0) {
#pragma unroll
        for (int o = 16; o; o >>= 1) {
            lmin = fminf(lmin, __shfl_xor_sync(0xFFFFFFFFu, lmin, o));
            lmax = fmaxf(lmax, __shfl_xor_sync(0xFFFFFFFFu, lmax, o));
        }
        __shared__ float red[16];
        const int wid = tid >> 5;
        if ((tid & 31) == 0) { red[wid] = lmin; red[8 + wid] = lmax; }
        __syncthreads();
        if (tid == 0) {
            float m0 = red[0], m1 = red[8];
#pragma unroll
            for (int i = 1; i < 8; ++i) {
                m0 = fminf(m0, red[i]);
                m1 = fmaxf(m1, red[8 + i]);
            }
            int lid = blockIdx.x + 8 * (blockIdx.y + 32 * blockIdx.z);
            g_pmin[lid] = m0;
            g_pmax[lid] = m1;
        }
    }
}

extern "C" void kernel_launch(void* const* d_in, const int* in_sizes, int n_in,
                              void* d_out, int out_size) {
    const float* x = (const float*)d_in[0];
    float* out = (float*)d_out;

    dim3 grid(OUT_W / TX, OUT_H / TY, NB * NC);   // 8 x 32 x 96
    k_resize<0><<<grid, 256>>>(x, nullptr);       // resize + per-tile min/max
    k_reduce<<<NB, 256>>>();                      // per-image min/max
    k_resize<1><<<grid, 256>>>(x, out);           // resize + renorm + f32(u8) store
}